// round 3
// baseline (speedup 1.0000x reference)
#include <cuda_runtime.h>

#define BN 65536
#define DD 512
#define CC 50
#define NE (BN + CC)
#define FK 10

// ---------------- device state (no allocations allowed) ----------------
__device__ double g_sum_ent;
__device__ float  g_ent[NE];
__device__ float  g_conf[NE];
__device__ int    g_lab[NE];
__device__ unsigned char g_consist[BN];
__device__ float  g_scale[BN];                 // 20 / max(||feat_i||, 1e-12)
__device__ unsigned long long g_key[NE];
__device__ unsigned g_hist[2][256];
__device__ unsigned g_prefix[2];
__device__ int      g_rem[2];
__device__ float    g_frac, g_thr, g_conf_thr;
__device__ int      g_kept_idx[CC * FK];
__device__ float    g_kept_w[CC * FK];
__device__ float    g_centroids[CC * DD];

// ---------------- helpers ----------------
__device__ __forceinline__ void ffma2(unsigned long long &d,
                                      unsigned long long a,
                                      unsigned long long b) {
    asm("fma.rn.f32x2 %0, %1, %2, %0;" : "+l"(d) : "l"(a), "l"(b));
}
__device__ __forceinline__ float pairsum(unsigned long long v) {
    float lo, hi;
    asm("mov.b64 {%0,%1}, %2;" : "=f"(lo), "=f"(hi) : "l"(v));
    return lo + hi;
}
__device__ __forceinline__ unsigned fkey(float f) {
    unsigned u = __float_as_uint(f);
    return (u & 0x80000000u) ? ~u : (u | 0x80000000u);
}
__device__ __forceinline__ float funkey(unsigned u) {
    return (u & 0x80000000u) ? __uint_as_float(u ^ 0x80000000u)
                             : __uint_as_float(~u);
}

// ---------------- 1) warmup memory stats: wl = W@W.T + b ----------------
__global__ void k_warmup(const float* __restrict__ W, const float* __restrict__ b) {
    int c1 = blockIdx.x, tid = threadIdx.x;  // 50 blocks x 64 threads
    __shared__ float sw[DD];
    __shared__ float sl[CC];
    for (int k = tid; k < DD; k += 64) sw[k] = W[(size_t)c1 * DD + k];
    __syncthreads();
    if (tid < CC) {
        const float* wj = W + (size_t)tid * DD;
        float acc = 0.f;
        for (int k = 0; k < DD; k++) acc += sw[k] * wj[k];
        sl[tid] = acc + b[tid];
    }
    __syncthreads();
    if (tid == 0) {
        float mx = sl[0]; int arg = 0;
        for (int c = 1; c < CC; c++) if (sl[c] > mx) { mx = sl[c]; arg = c; }
        float se = 0.f, sw2 = 0.f;
        for (int c = 0; c < CC; c++) {
            float e = __expf(sl[c] - mx);
            se += e; sw2 += e * sl[c];
        }
        float lse = mx + __logf(se);
        g_ent[c1]  = lse - sw2 / se;
        g_conf[c1] = 1.0f / se;
        g_lab[c1]  = arg;
    }
    if (c1 == 0) {   // per-replay state reset
        if (tid == 0) g_sum_ent = 0.0;
        for (int i = tid; i < 512; i += 64) ((unsigned*)g_hist)[i] = 0u;
    }
}

// ---------------- 2) main GEMM + per-row stats ----------------
__global__ __launch_bounds__(256, 1)
void k_main(const float* __restrict__ feat, const float* __restrict__ lraw,
            const float* __restrict__ laug, const float* __restrict__ W,
            const float* __restrict__ b) {
    extern __shared__ float sW[];                 // CC*DD + CC
    float* sB = sW + CC * DD;
    int tid = threadIdx.x;
    for (int i = tid; i < CC * DD / 4; i += 256)
        ((float4*)sW)[i] = ((const float4*)W)[i];
    for (int i = tid; i < CC; i += 256) sB[i] = b[i];
    __syncthreads();

    int row = blockIdx.x * 256 + tid;
    const ulonglong2* fr = (const ulonglong2*)(feat + (size_t)row * DD);

    unsigned long long acc[CC];
#pragma unroll
    for (int c = 0; c < CC; c++) acc[c] = 0ull;
    unsigned long long asq = 0ull;

#pragma unroll 1
    for (int it = 0; it < DD / 4; ++it) {         // 4 K-values per iter
        ulonglong2 a = fr[it];
        ffma2(asq, a.x, a.x);
        ffma2(asq, a.y, a.y);
        const float* wbase = sW + it * 4;
#pragma unroll
        for (int c = 0; c < CC; c++) {
            ulonglong2 w = *(const ulonglong2*)(wbase + c * DD);
            ffma2(acc[c], a.x, w.x);
            ffma2(acc[c], a.y, w.y);
        }
    }

    // ---- epilogue: softmax stats ----
    float lg[CC];
#pragma unroll
    for (int c = 0; c < CC; c++) lg[c] = pairsum(acc[c]) + sB[c];
    float mx = lg[0]; int arg = 0;
#pragma unroll
    for (int c = 1; c < CC; c++) if (lg[c] > mx) { mx = lg[c]; arg = c; }
    float se = 0.f, sl = 0.f;
#pragma unroll
    for (int c = 0; c < CC; c++) {
        float e = __expf(lg[c] - mx);
        se += e; sl += e * lg[c];
    }
    float lse  = mx + __logf(se);
    float ent  = lse - sl / se;
    float pmax = 1.0f / se;
    float inv  = 1.0f / fmaxf(sqrtf(pairsum(asq)), 1e-12f);

    // ---- dual-view argmax consistency ----
    const float2* r2 = (const float2*)(lraw + (size_t)row * CC);
    const float2* a2 = (const float2*)(laug + (size_t)row * CC);
    float b1 = -3.4e38f, b2 = -3.4e38f; int i1 = 0, i2 = 0;
#pragma unroll
    for (int j = 0; j < CC / 2; j++) {
        float2 v = r2[j];
        if (v.x > b1) { b1 = v.x; i1 = 2 * j; }
        if (v.y > b1) { b1 = v.y; i1 = 2 * j + 1; }
        float2 u = a2[j];
        if (u.x > b2) { b2 = u.x; i2 = 2 * j; }
        if (u.y > b2) { b2 = u.y; i2 = 2 * j + 1; }
    }

    g_consist[row]  = (unsigned char)(i1 == i2);
    g_ent[CC + row] = ent;
    g_conf[CC + row] = pmax;
    g_lab[CC + row]  = arg;
    g_scale[row]     = 20.0f * inv;

    __shared__ double red[256];
    red[tid] = (double)ent;
    __syncthreads();
    for (int s = 128; s; s >>= 1) {
        if (tid < s) red[tid] += red[tid + s];
        __syncthreads();
    }
    if (tid == 0) atomicAdd(&g_sum_ent, red[0]);
}

// ---------------- 3) branch / select init ----------------
__global__ void k_branch() {
    float m = (float)(g_sum_ent / (double)BN);
    float q = (m >= 0.45f) ? 0.25f : ((m >= 0.38f) ? 0.3f : 0.4f);
    g_conf_thr = (m >= 0.45f) ? 0.72f : 0.62f;
    float pos = q * (float)(BN - 1);
    float lof = floorf(pos);
    int lo = (int)lof;
    g_frac = pos - lof;
    int hi = min(lo + 1, BN - 1);
    g_prefix[0] = 0u; g_prefix[1] = 0u;
    g_rem[0] = lo;    g_rem[1] = hi;
}

// ---------------- 4) 2-rank MSB radix select ----------------
__global__ void k_hist(int shift) {
    __shared__ unsigned h0[256], h1[256];
    int tid = threadIdx.x;
    h0[tid] = 0u; h1[tid] = 0u;
    __syncthreads();
    unsigned hm = (shift >= 24) ? 0u : (0xFFFFFFFFu << (shift + 8));
    unsigned p0 = g_prefix[0], p1 = g_prefix[1];
    for (int i = blockIdx.x * 256 + tid; i < BN; i += gridDim.x * 256) {
        unsigned u = fkey(g_ent[CC + i]);
        unsigned d = (u >> shift) & 255u;
        if ((u & hm) == p0) atomicAdd(&h0[d], 1u);
        if ((u & hm) == p1) atomicAdd(&h1[d], 1u);
    }
    __syncthreads();
    if (h0[tid]) atomicAdd(&g_hist[0][tid], h0[tid]);
    if (h1[tid]) atomicAdd(&g_hist[1][tid], h1[tid]);
}

__global__ void k_resolve(int shift, int last) {
    for (int s = 0; s < 2; s++) {
        int rem = g_rem[s];
        unsigned pre = g_prefix[s];
        int bsel = 255;
        for (int bb = 0; bb < 256; bb++) {
            unsigned c = g_hist[s][bb];
            if ((unsigned)rem < c) { bsel = bb; break; }
            rem -= (int)c;
            g_hist[s][bb] = 0u;
        }
        for (int bb = bsel; bb < 256; bb++) g_hist[s][bb] = 0u;
        g_rem[s] = rem;
        g_prefix[s] = pre | ((unsigned)bsel << shift);
    }
    if (last) {
        float v0 = funkey(g_prefix[0]);
        float v1 = funkey(g_prefix[1]);
        g_thr = v0 * (1.0f - g_frac) + v1 * g_frac;
    }
}

// ---------------- 5) validity + sort keys ----------------
__global__ void k_keys() {
    int e = blockIdx.x * 256 + threadIdx.x;
    if (e >= NE) return;
    bool valid;
    if (e < CC) valid = true;
    else valid = (g_ent[e] <= g_thr) && g_consist[e - CC] && (g_conf[e] >= g_conf_thr);
    g_key[e] = valid ? ((((unsigned long long)fkey(g_ent[e])) << 32) | (unsigned)e)
                     : ~0ull;
}

// ---------------- 6) per-class top-10 lowest-entropy ----------------
__global__ void k_topk() {
    int c = blockIdx.x, tid = threadIdx.x;  // 50 blocks x 256
    unsigned long long loc[FK];
#pragma unroll
    for (int j = 0; j < FK; j++) loc[j] = ~0ull;

    for (int e = tid; e < NE; e += 256) {
        if (g_lab[e] != c) continue;
        unsigned long long k = g_key[e];
        if (k < loc[FK - 1]) {
            loc[FK - 1] = k;
#pragma unroll
            for (int j = FK - 1; j > 0; j--) {
                if (loc[j] < loc[j - 1]) {
                    unsigned long long t = loc[j];
                    loc[j] = loc[j - 1];
                    loc[j - 1] = t;
                }
            }
        }
    }

    __shared__ unsigned long long sh[256];
    int ptr = 0;
    for (int j = 0; j < FK; j++) {
        sh[tid] = (ptr < FK) ? loc[ptr] : ~0ull;
        __syncthreads();
        for (int s = 128; s; s >>= 1) {
            if (tid < s) {
                unsigned long long x = sh[tid], y = sh[tid + s];
                sh[tid] = (y < x) ? y : x;
            }
            __syncthreads();
        }
        unsigned long long win = sh[0];
        __syncthreads();
        if (ptr < FK && loc[ptr] == win && win != ~0ull) ptr++;
        if (tid == 0) {
            if (win != ~0ull) {
                int idx = (int)(win & 0xffffffffu);
                g_kept_idx[c * FK + j] = idx;
                g_kept_w[c * FK + j] = fmaxf(g_conf[idx], 1e-6f);
            } else {
                g_kept_idx[c * FK + j] = -1;
            }
        }
    }
}

// ---------------- 7) confidence-weighted centroids ----------------
__global__ void k_centroid(const float* __restrict__ feat, const float* __restrict__ W) {
    int c = blockIdx.x, tid = threadIdx.x;  // 50 blocks x 256
    __shared__ float red[256];
    float a0 = 0.f, a1 = 0.f;
    for (int j = 0; j < FK; j++) {
        int idx = g_kept_idx[c * FK + j];     // uniform across block
        if (idx >= 0) {
            const float* v = (idx < CC) ? (W + (size_t)idx * DD)
                                        : (feat + (size_t)(idx - CC) * DD);
            float x0 = v[tid], x1 = v[tid + 256];
            red[tid] = x0 * x0 + x1 * x1;
            __syncthreads();
            for (int s = 128; s; s >>= 1) {
                if (tid < s) red[tid] += red[tid + s];
                __syncthreads();
            }
            float w = g_kept_w[c * FK + j] / fmaxf(sqrtf(red[0]), 1e-12f);
            __syncthreads();
            a0 += w * x0;
            a1 += w * x1;
        }
    }
    red[tid] = a0 * a0 + a1 * a1;
    __syncthreads();
    for (int s = 128; s; s >>= 1) {
        if (tid < s) red[tid] += red[tid + s];
        __syncthreads();
    }
    float n = fmaxf(sqrtf(red[0]), 1e-12f);
    g_centroids[(size_t)c * DD + tid]       = a0 / n;
    g_centroids[(size_t)c * DD + tid + 256] = a1 / n;
}

// ---------------- 8) output GEMM: 20 * normalize(feat) @ centroids.T ----------------
__global__ __launch_bounds__(256, 1)
void k_out(const float* __restrict__ feat, float* __restrict__ out) {
    extern __shared__ float sC[];             // CC*DD
    int tid = threadIdx.x;
    for (int i = tid; i < CC * DD / 4; i += 256)
        ((float4*)sC)[i] = ((const float4*)g_centroids)[i];
    __syncthreads();

    int row = blockIdx.x * 256 + tid;
    const ulonglong2* fr = (const ulonglong2*)(feat + (size_t)row * DD);

    unsigned long long acc[CC];
#pragma unroll
    for (int c = 0; c < CC; c++) acc[c] = 0ull;

#pragma unroll 1
    for (int it = 0; it < DD / 4; ++it) {
        ulonglong2 a = fr[it];
        const float* cb = sC + it * 4;
#pragma unroll
        for (int c = 0; c < CC; c++) {
            ulonglong2 w = *(const ulonglong2*)(cb + c * DD);
            ffma2(acc[c], a.x, w.x);
            ffma2(acc[c], a.y, w.y);
        }
    }

    float s = g_scale[row];
    float2* o2 = (float2*)(out + (size_t)row * CC);
#pragma unroll
    for (int j = 0; j < CC / 2; j++) {
        float2 v;
        v.x = s * pairsum(acc[2 * j]);
        v.y = s * pairsum(acc[2 * j + 1]);
        o2[j] = v;
    }
}

// ---------------- host ----------------
extern "C" void kernel_launch(void* const* d_in, const int* in_sizes, int n_in,
                              void* d_out, int out_size) {
    const float* feat = (const float*)d_in[0];
    const float* lraw = (const float*)d_in[1];
    const float* laug = (const float*)d_in[2];
    const float* W    = (const float*)d_in[3];
    const float* b    = (const float*)d_in[4];
    float* out = (float*)d_out;

    size_t shmem = (size_t)CC * DD * sizeof(float) + 256;
    cudaFuncSetAttribute(k_main, cudaFuncAttributeMaxDynamicSharedMemorySize, (int)shmem);
    cudaFuncSetAttribute(k_out,  cudaFuncAttributeMaxDynamicSharedMemorySize, (int)shmem);

    k_warmup<<<CC, 64>>>(W, b);
    k_main<<<BN / 256, 256, shmem>>>(feat, lraw, laug, W, b);
    k_branch<<<1, 1>>>();
    for (int r = 0; r < 4; r++) {
        int shift = 24 - 8 * r;
        k_hist<<<128, 256>>>(shift);
        k_resolve<<<1, 1>>>(shift, (r == 3) ? 1 : 0);
    }
    k_keys<<<(NE + 255) / 256, 256>>>();
    k_topk<<<CC, 256>>>();
    k_centroid<<<CC, 256>>>(feat, W);
    k_out<<<BN / 256, 256, shmem>>>(feat, out);
}

// round 4
// speedup vs baseline: 1.4391x; 1.4391x over previous
#include <cuda_runtime.h>

#define BN 65536
#define DD 512
#define CC 50
#define NE (BN + CC)
#define FK 10
#define CPAD 52              // classes padded to 52 (13 float4 per k-row)
#define NPAIR 26             // 26 class pairs
#define HB 65536             // histogram bins
#define HSCALE 16384.0f      // bins per unit entropy (range [0,4))
#define CAP 8192             // candidate cap per rank

// ---------------- device state (no allocations allowed) ----------------
__device__ double g_sum_ent;
__device__ float  g_ent[NE];
__device__ float  g_conf[NE];
__device__ int    g_lab[NE];
__device__ unsigned char g_consist[BN];
__device__ float  g_scale[BN];                 // 20 / max(||feat_i||, 1e-12)
__device__ unsigned long long g_key[NE];
__device__ unsigned g_hist16[HB];
__device__ int      g_rank[2];
__device__ int      g_bucket[2];
__device__ int      g_rwith[2];
__device__ int      g_cand_n[2];
__device__ float    g_cand[2][CAP];
__device__ float    g_qval[2];
__device__ float    g_frac, g_thr, g_conf_thr;
__device__ int      g_kept_idx[CC * FK];
__device__ float    g_kept_w[CC * FK];
__device__ __align__(16) float g_centT[DD * CPAD];   // transposed padded centroids

// ---------------- helpers ----------------
__device__ __forceinline__ void ffma2(unsigned long long &d,
                                      unsigned long long a,
                                      unsigned long long b) {
    asm("fma.rn.f32x2 %0, %1, %2, %0;" : "+l"(d) : "l"(a), "l"(b));
}
__device__ __forceinline__ unsigned long long splat2(float f) {
    unsigned long long r;
    asm("mov.b64 %0, {%1,%1};" : "=l"(r) : "f"(f));
    return r;
}
__device__ __forceinline__ unsigned long long pack2(float x, float y) {
    unsigned long long r;
    asm("mov.b64 %0, {%1,%2};" : "=l"(r) : "f"(x), "f"(y));
    return r;
}
__device__ __forceinline__ void unpack2(unsigned long long v, float &lo, float &hi) {
    asm("mov.b64 {%0,%1}, %2;" : "=f"(lo), "=f"(hi) : "l"(v));
}
__device__ __forceinline__ unsigned fkey(float f) {
    unsigned u = __float_as_uint(f);
    return (u & 0x80000000u) ? ~u : (u | 0x80000000u);
}
__device__ __forceinline__ int ent_bucket(float e) {
    int b = (int)(e * HSCALE);
    return min(max(b, 0), HB - 1);
}

// ---------------- 0) no-ops to position ncu's -s 5 -c 1 window on k_main ----
__global__ void k_noop() {}

// ---------------- 1) warmup memory stats: wl = W@W.T + b ----------------
__global__ void k_warmup(const float* __restrict__ W, const float* __restrict__ b) {
    int c1 = blockIdx.x, tid = threadIdx.x;  // 50 blocks x 64 threads
    __shared__ float sw[DD];
    __shared__ float sl[CC];
    for (int k = tid; k < DD; k += 64) sw[k] = W[(size_t)c1 * DD + k];
    __syncthreads();
    if (tid < CC) {
        const float* wj = W + (size_t)tid * DD;
        float acc = 0.f;
        for (int k = 0; k < DD; k++) acc += sw[k] * wj[k];
        sl[tid] = acc + b[tid];
    }
    __syncthreads();
    if (tid == 0) {
        float mx = sl[0]; int arg = 0;
        for (int c = 1; c < CC; c++) if (sl[c] > mx) { mx = sl[c]; arg = c; }
        float se = 0.f, sw2 = 0.f;
        for (int c = 0; c < CC; c++) {
            float e = __expf(sl[c] - mx);
            se += e; sw2 += e * sl[c];
        }
        float lse = mx + __logf(se);
        g_ent[c1]  = lse - sw2 / se;
        g_conf[c1] = 1.0f / se;
        g_lab[c1]  = arg;
    }
    // per-replay state reset: histogram + running sum
    for (int i = blockIdx.x * 64 + tid; i < HB; i += CC * 64) g_hist16[i] = 0u;
    if (c1 == 0 && tid == 0) g_sum_ent = 0.0;
}

// ---------------- 2) main GEMM (2 rows/thread, class-paired FFMA2) --------
__global__ __launch_bounds__(256, 1)
void k_main(const float* __restrict__ feat, const float* __restrict__ lraw,
            const float* __restrict__ laug, const float* __restrict__ W,
            const float* __restrict__ b) {
    extern __shared__ float sWt[];                // [DD][CPAD] transposed W
    __shared__ float sB[CPAD];
    __shared__ double red[256];
    int tid = threadIdx.x;

    // build W^T with padded class dim (pads zeroed)
    for (int idx = tid; idx < CC * DD; idx += 256) {
        int c = idx >> 9, k = idx & 511;          // gmem coalesced over k
        sWt[k * CPAD + c] = W[idx];
    }
    for (int k = tid; k < DD; k += 256) {
        sWt[k * CPAD + 50] = 0.f;
        sWt[k * CPAD + 51] = 0.f;
    }
    if (tid < CC) sB[tid] = b[tid];
    __syncthreads();

    int row0 = blockIdx.x * 512 + tid;
    int row1 = row0 + 256;
    const float4* f0p = (const float4*)(feat + (size_t)row0 * DD);
    const float4* f1p = (const float4*)(feat + (size_t)row1 * DD);

    unsigned long long acc0[NPAIR], acc1[NPAIR];
#pragma unroll
    for (int j = 0; j < NPAIR; j++) { acc0[j] = 0ull; acc1[j] = 0ull; }
    float nrm0 = 0.f, nrm1 = 0.f;

    float4 cur0 = f0p[0], cur1 = f1p[0];
    float4 nx0  = f0p[1], nx1  = f1p[1];

#pragma unroll 1
    for (int it = 0; it < DD / 4; ++it) {
        int ip = min(it + 2, DD / 4 - 1);
        float4 pf0 = f0p[ip], pf1 = f1p[ip];
        float a0v[4] = {cur0.x, cur0.y, cur0.z, cur0.w};
        float a1v[4] = {cur1.x, cur1.y, cur1.z, cur1.w};
#pragma unroll
        for (int kk = 0; kk < 4; kk++) {
            unsigned long long s0 = splat2(a0v[kk]);
            unsigned long long s1 = splat2(a1v[kk]);
            nrm0 = fmaf(a0v[kk], a0v[kk], nrm0);
            nrm1 = fmaf(a1v[kk], a1v[kk], nrm1);
            const float4* wr = (const float4*)(sWt + (it * 4 + kk) * CPAD);
#pragma unroll
            for (int j = 0; j < 13; j++) {
                float4 w = wr[j];
                unsigned long long wlo = pack2(w.x, w.y);
                unsigned long long whi = pack2(w.z, w.w);
                ffma2(acc0[2 * j],     s0, wlo);
                ffma2(acc0[2 * j + 1], s0, whi);
                ffma2(acc1[2 * j],     s1, wlo);
                ffma2(acc1[2 * j + 1], s1, whi);
            }
        }
        cur0 = nx0; cur1 = nx1;
        nx0 = pf0;  nx1 = pf1;
    }

    float entv[2];
#pragma unroll
    for (int rr = 0; rr < 2; rr++) {
        int row = rr ? row1 : row0;
        float nrm = rr ? nrm1 : nrm0;
        float lg[CC];
#pragma unroll
        for (int j = 0; j < 25; j++) {
            float lo, hi;
            unpack2(rr ? acc1[j] : acc0[j], lo, hi);
            lg[2 * j]     = lo + sB[2 * j];
            lg[2 * j + 1] = hi + sB[2 * j + 1];
        }
        float mx = lg[0]; int arg = 0;
#pragma unroll
        for (int c = 1; c < CC; c++) if (lg[c] > mx) { mx = lg[c]; arg = c; }
        float se = 0.f, sl = 0.f;
#pragma unroll
        for (int c = 0; c < CC; c++) {
            float e = __expf(lg[c] - mx);
            se += e; sl += e * lg[c];
        }
        float lse  = mx + __logf(se);
        float ent  = lse - sl / se;
        float pmax = 1.0f / se;
        float inv  = 1.0f / fmaxf(sqrtf(nrm), 1e-12f);

        const float2* r2 = (const float2*)(lraw + (size_t)row * CC);
        const float2* a2 = (const float2*)(laug + (size_t)row * CC);
        float b1 = -3.4e38f, b2 = -3.4e38f; int i1 = 0, i2 = 0;
#pragma unroll
        for (int j = 0; j < CC / 2; j++) {
            float2 v = r2[j];
            if (v.x > b1) { b1 = v.x; i1 = 2 * j; }
            if (v.y > b1) { b1 = v.y; i1 = 2 * j + 1; }
            float2 u = a2[j];
            if (u.x > b2) { b2 = u.x; i2 = 2 * j; }
            if (u.y > b2) { b2 = u.y; i2 = 2 * j + 1; }
        }

        g_consist[row]   = (unsigned char)(i1 == i2);
        g_ent[CC + row]  = ent;
        g_conf[CC + row] = pmax;
        g_lab[CC + row]  = arg;
        g_scale[row]     = 20.0f * inv;
        atomicAdd(&g_hist16[ent_bucket(ent)], 1u);
        entv[rr] = ent;
    }

    red[tid] = (double)entv[0] + (double)entv[1];
    __syncthreads();
    for (int s = 128; s; s >>= 1) {
        if (tid < s) red[tid] += red[tid + s];
        __syncthreads();
    }
    if (tid == 0) atomicAdd(&g_sum_ent, red[0]);
}

// ---------------- 3) branch: dyn quantile target + conf threshold ---------
__global__ void k_branch() {
    float m = (float)(g_sum_ent / (double)BN);
    float q = (m >= 0.45f) ? 0.25f : ((m >= 0.38f) ? 0.3f : 0.4f);
    g_conf_thr = (m >= 0.45f) ? 0.72f : 0.62f;
    float pos = q * (float)(BN - 1);
    float lof = floorf(pos);
    int lo = (int)lof;
    g_frac = pos - lof;
    g_rank[0] = lo;
    g_rank[1] = min(lo + 1, BN - 1);
    g_cand_n[0] = 0;
    g_cand_n[1] = 0;
}

// ---------------- 4) histogram scan: find buckets of the 2 order stats ----
__global__ void k_scan() {
    int tid = threadIdx.x;                      // 1024 threads
    __shared__ unsigned sc[1024];
    int base = tid * (HB / 1024);
    unsigned local = 0;
    for (int j = 0; j < HB / 1024; j++) local += g_hist16[base + j];
    sc[tid] = local;
    __syncthreads();
    for (int off = 1; off < 1024; off <<= 1) {
        unsigned v = 0;
        if (tid >= off) v = sc[tid - off];
        __syncthreads();
        if (tid >= off) sc[tid] += v;
        __syncthreads();
    }
    unsigned incl = sc[tid];
    unsigned before = incl - local;
    for (int s = 0; s < 2; s++) {
        unsigned r = (unsigned)g_rank[s];
        if (before <= r && r < incl) {
            unsigned acc = before;
            for (int j = 0; j < HB / 1024; j++) {
                unsigned c = g_hist16[base + j];
                if (r < acc + c) {
                    g_bucket[s] = base + j;
                    g_rwith[s]  = (int)(r - acc);
                    break;
                }
                acc += c;
            }
        }
    }
}

// ---------------- 5) gather candidates in the target buckets --------------
__global__ void k_select() {
    int b0 = g_bucket[0], b1 = g_bucket[1];
    for (int i = blockIdx.x * blockDim.x + threadIdx.x; i < BN;
         i += gridDim.x * blockDim.x) {
        float e = g_ent[CC + i];
        int bb = ent_bucket(e);
        if (bb == b0) {
            int p = atomicAdd(&g_cand_n[0], 1);
            if (p < CAP) g_cand[0][p] = e;
        }
        if (bb == b1) {
            int p = atomicAdd(&g_cand_n[1], 1);
            if (p < CAP) g_cand[1][p] = e;
        }
    }
}

// ---------------- 6) exact selection inside bucket → threshold ------------
__global__ void k_pick() {
    __shared__ float cs[CAP];
    int tid = threadIdx.x;                       // 256 threads
    for (int s = 0; s < 2; s++) {
        int n = min(g_cand_n[s], CAP);
        for (int i = tid; i < n; i += 256) cs[i] = g_cand[s][i];
        __syncthreads();
        int r = g_rwith[s];
        for (int i = tid; i < n; i += 256) {
            float v = cs[i];
            int rank = 0;
            for (int j = 0; j < n; j++) {
                float u = cs[j];
                rank += (u < v) || (u == v && j < i);
            }
            if (rank == r) g_qval[s] = v;
        }
        __syncthreads();
    }
    if (tid == 0) {
        float f = g_frac;
        g_thr = g_qval[0] * (1.0f - f) + g_qval[1] * f;
    }
}

// ---------------- 7) validity + sort keys ----------------
__global__ void k_keys() {
    int e = blockIdx.x * 256 + threadIdx.x;
    if (e >= NE) return;
    bool valid;
    if (e < CC) valid = true;
    else valid = (g_ent[e] <= g_thr) && g_consist[e - CC] && (g_conf[e] >= g_conf_thr);
    g_key[e] = valid ? ((((unsigned long long)fkey(g_ent[e])) << 32) | (unsigned)e)
                     : ~0ull;
}

// ---------------- 8) per-class top-10 lowest-entropy ----------------
__global__ void k_topk() {
    int c = blockIdx.x, tid = threadIdx.x;  // 50 blocks x 256
    unsigned long long loc[FK];
#pragma unroll
    for (int j = 0; j < FK; j++) loc[j] = ~0ull;

    for (int e = tid; e < NE; e += 256) {
        if (g_lab[e] != c) continue;
        unsigned long long k = g_key[e];
        if (k < loc[FK - 1]) {
            loc[FK - 1] = k;
#pragma unroll
            for (int j = FK - 1; j > 0; j--) {
                if (loc[j] < loc[j - 1]) {
                    unsigned long long t = loc[j];
                    loc[j] = loc[j - 1];
                    loc[j - 1] = t;
                }
            }
        }
    }

    __shared__ unsigned long long sh[256];
    int ptr = 0;
    for (int j = 0; j < FK; j++) {
        sh[tid] = (ptr < FK) ? loc[ptr] : ~0ull;
        __syncthreads();
        for (int s = 128; s; s >>= 1) {
            if (tid < s) {
                unsigned long long x = sh[tid], y = sh[tid + s];
                sh[tid] = (y < x) ? y : x;
            }
            __syncthreads();
        }
        unsigned long long win = sh[0];
        __syncthreads();
        if (ptr < FK && loc[ptr] == win && win != ~0ull) ptr++;
        if (tid == 0) {
            if (win != ~0ull) {
                int idx = (int)(win & 0xffffffffu);
                g_kept_idx[c * FK + j] = idx;
                g_kept_w[c * FK + j] = fmaxf(g_conf[idx], 1e-6f);
            } else {
                g_kept_idx[c * FK + j] = -1;
            }
        }
    }
}

// ---------------- 9) confidence-weighted centroids (transposed out) -------
__global__ void k_centroid(const float* __restrict__ feat, const float* __restrict__ W) {
    int c = blockIdx.x, tid = threadIdx.x;  // 50 blocks x 256
    __shared__ float red[256];
    float a0 = 0.f, a1 = 0.f;
    for (int j = 0; j < FK; j++) {
        int idx = g_kept_idx[c * FK + j];     // uniform across block
        if (idx >= 0) {
            const float* v = (idx < CC) ? (W + (size_t)idx * DD)
                                        : (feat + (size_t)(idx - CC) * DD);
            float x0 = v[tid], x1 = v[tid + 256];
            red[tid] = x0 * x0 + x1 * x1;
            __syncthreads();
            for (int s = 128; s; s >>= 1) {
                if (tid < s) red[tid] += red[tid + s];
                __syncthreads();
            }
            float w = g_kept_w[c * FK + j] / fmaxf(sqrtf(red[0]), 1e-12f);
            __syncthreads();
            a0 += w * x0;
            a1 += w * x1;
        }
    }
    red[tid] = a0 * a0 + a1 * a1;
    __syncthreads();
    for (int s = 128; s; s >>= 1) {
        if (tid < s) red[tid] += red[tid + s];
        __syncthreads();
    }
    float n = fmaxf(sqrtf(red[0]), 1e-12f);
    g_centT[(size_t)tid * CPAD + c]         = a0 / n;
    g_centT[(size_t)(tid + 256) * CPAD + c] = a1 / n;
    if (c == 0) {   // zero pad columns
        g_centT[(size_t)tid * CPAD + 50] = 0.f;
        g_centT[(size_t)tid * CPAD + 51] = 0.f;
        g_centT[(size_t)(tid + 256) * CPAD + 50] = 0.f;
        g_centT[(size_t)(tid + 256) * CPAD + 51] = 0.f;
    }
}

// ---------------- 10) output GEMM: 20 * normalize(feat) @ centroids.T -----
__global__ __launch_bounds__(256, 1)
void k_out(const float* __restrict__ feat, float* __restrict__ out) {
    extern __shared__ float sC[];             // [DD][CPAD]
    int tid = threadIdx.x;
    for (int i = tid; i < DD * CPAD / 4; i += 256)
        ((float4*)sC)[i] = ((const float4*)g_centT)[i];
    __syncthreads();

    int row0 = blockIdx.x * 512 + tid;
    int row1 = row0 + 256;
    const float4* f0p = (const float4*)(feat + (size_t)row0 * DD);
    const float4* f1p = (const float4*)(feat + (size_t)row1 * DD);

    unsigned long long acc0[NPAIR], acc1[NPAIR];
#pragma unroll
    for (int j = 0; j < NPAIR; j++) { acc0[j] = 0ull; acc1[j] = 0ull; }

    float4 cur0 = f0p[0], cur1 = f1p[0];
    float4 nx0  = f0p[1], nx1  = f1p[1];

#pragma unroll 1
    for (int it = 0; it < DD / 4; ++it) {
        int ip = min(it + 2, DD / 4 - 1);
        float4 pf0 = f0p[ip], pf1 = f1p[ip];
        float a0v[4] = {cur0.x, cur0.y, cur0.z, cur0.w};
        float a1v[4] = {cur1.x, cur1.y, cur1.z, cur1.w};
#pragma unroll
        for (int kk = 0; kk < 4; kk++) {
            unsigned long long s0 = splat2(a0v[kk]);
            unsigned long long s1 = splat2(a1v[kk]);
            const float4* wr = (const float4*)(sC + (it * 4 + kk) * CPAD);
#pragma unroll
            for (int j = 0; j < 13; j++) {
                float4 w = wr[j];
                unsigned long long wlo = pack2(w.x, w.y);
                unsigned long long whi = pack2(w.z, w.w);
                ffma2(acc0[2 * j],     s0, wlo);
                ffma2(acc0[2 * j + 1], s0, whi);
                ffma2(acc1[2 * j],     s1, wlo);
                ffma2(acc1[2 * j + 1], s1, whi);
            }
        }
        cur0 = nx0; cur1 = nx1;
        nx0 = pf0;  nx1 = pf1;
    }

#pragma unroll
    for (int rr = 0; rr < 2; rr++) {
        int row = rr ? row1 : row0;
        float s = g_scale[row];
        float2* o2 = (float2*)(out + (size_t)row * CC);
#pragma unroll
        for (int j = 0; j < 25; j++) {
            float lo, hi;
            unpack2(rr ? acc1[j] : acc0[j], lo, hi);
            float2 v; v.x = s * lo; v.y = s * hi;
            o2[j] = v;
        }
    }
}

// ---------------- host ----------------
extern "C" void kernel_launch(void* const* d_in, const int* in_sizes, int n_in,
                              void* d_out, int out_size) {
    const float* feat = (const float*)d_in[0];
    const float* lraw = (const float*)d_in[1];
    const float* laug = (const float*)d_in[2];
    const float* W    = (const float*)d_in[3];
    const float* b    = (const float*)d_in[4];
    float* out = (float*)d_out;

    size_t shmem = (size_t)DD * CPAD * sizeof(float);   // 106,496 B
    cudaFuncSetAttribute(k_main, cudaFuncAttributeMaxDynamicSharedMemorySize, (int)shmem);
    cudaFuncSetAttribute(k_out,  cudaFuncAttributeMaxDynamicSharedMemorySize, (int)shmem);

    // 4 no-ops so ncu (-s 5 -c 1) profiles k_main (launch #6)
    k_noop<<<1, 32>>>();
    k_noop<<<1, 32>>>();
    k_noop<<<1, 32>>>();
    k_noop<<<1, 32>>>();

    k_warmup<<<CC, 64>>>(W, b);
    k_main<<<BN / 512, 256, shmem>>>(feat, lraw, laug, W, b);
    k_branch<<<1, 1>>>();
    k_scan<<<1, 1024>>>();
    k_select<<<64, 256>>>();
    k_pick<<<1, 256>>>();
    k_keys<<<(NE + 255) / 256, 256>>>();
    k_topk<<<CC, 256>>>();
    k_centroid<<<CC, 256>>>(feat, W);
    k_out<<<BN / 512, 256, shmem>>>(feat, out);
}